// round 13
// baseline (speedup 1.0000x reference)
#include <cuda_runtime.h>
#include <cuda_bf16.h>

// Problem constants (fixed by the reference)
#define GRID_NX   48
#define GRID_NY   48
#define GRID_NZ   48
#define N_GRID    (GRID_NX * GRID_NY * GRID_NZ)   // 110592
#define SPACING   0.5f
#define A_MAX     800
#define NG        6
#define MAX_PAIRS (A_MAX * NG)                    // 4800

// Cull threshold: drop pair for a tile when |c|*min_d2 > T  (contribution < 2^-18 * w)
#define T_CUT     18.0f

// Tile geometry: 8 x 8 x 4 grid points per tile (432 tiles)
#define TILE_X 8
#define TILE_Y 8
#define TILE_Z 4
#define NBX (GRID_NX / TILE_X)   // 6
#define NBY (GRID_NY / TILE_Y)   // 6
#define NBZ (GRID_NZ / TILE_Z)   // 12
#define N_TILES (NBX * NBY * NBZ)

#define NWARP  16                // pair-range partitions (one warp each, 512 thr)
#define CHUNK  32                // pairs culled per warp-chunk (one ballot)

// Scratch (__device__ globals, no allocation)
__device__ float4 g_cull[MAX_PAIRS];        // px, py, pz, d2cut (-1 => inactive)
// Separable 1-D tables. g_exp is PAIRED layout per x-tile:
//   g_exp[p][tile*8 + slot*2 + half] = Ex(tile*8 + slot + 4*half)
// so the two float4s of a tile == (Ex(i), Ex(i+4)) pairs for i=0..3,
// matching the packed accumulator layout accp_i = (x_i, x_{i+4}).
__device__ float g_exp[MAX_PAIRS][48];      // Ex, paired layout
__device__ float g_eyw[MAX_PAIRS][48];      // w * Ey
__device__ float g_ez [MAX_PAIRS][48];      // Ez

__device__ __forceinline__ float ex2f(float x) {
    float r;
    asm("ex2.approx.f32 %0, %1;" : "=f"(r) : "f"(x));
    return r;
}

// Packed f32x2 helpers (Blackwell)
__device__ __forceinline__ unsigned long long pk(float lo, float hi) {
    unsigned long long r;
    asm("mov.b64 %0, {%1, %2};" : "=l"(r) : "f"(lo), "f"(hi));
    return r;
}
__device__ __forceinline__ void unpk(float& lo, float& hi, unsigned long long v) {
    asm("mov.b64 {%0, %1}, %2;" : "=f"(lo), "=f"(hi) : "l"(v));
}
__device__ __forceinline__ unsigned long long fma2(unsigned long long a,
                                                   unsigned long long b,
                                                   unsigned long long c) {
    unsigned long long r;
    asm("fma.rn.f32x2 %0, %1, %2, %3;" : "=l"(r) : "l"(a), "l"(b), "l"(c));
    return r;
}

// ---------------------------------------------------------------------------
// Kernel 1: build cull table + separable 1-D exp tables.
// 64 threads per pair (indices 48..63 idle) -- power-of-2 indexing avoids
// integer div/mod. 3 EX2 per active thread, fully parallel.
// ---------------------------------------------------------------------------
__global__ __launch_bounds__(256)
void build_tables(const float* __restrict__ X,
                  const float* __restrict__ aw,
                  const float* __restrict__ bw,
                  const int*   __restrict__ elements,
                  const int*   __restrict__ C_expand,
                  int npairs)
{
    const float LOG2E = 1.4426950408889634f;
    int t = blockIdx.x * 256 + threadIdx.x;
    int p   = t >> 6;
    int i48 = t & 63;
    if (p >= npairs || i48 >= 48) return;
    int a = (p * (int)((1u << 16) / NG + 1)) >> 16;   // p / 6 for p < 4800
    // exact check (cheap correction, avoids div): a = p/NG
    if (a * NG > p) a--;
    else if ((a + 1) * NG <= p) a++;

    float c = bw[p] * LOG2E;          // c < 0
    float w = aw[p];
    float px = X[a * 3 + 0];
    float py = X[a * 3 + 1];
    float pz = X[a * 3 + 2];

    float g = (float)i48 * SPACING;
    float dx = g - px, dy = g - py, dz = g - pz;

    // Ex in paired layout
    int tile = i48 >> 3, ii = i48 & 7;
    int slot = ii & 3, half = ii >> 2;
    g_exp[p][tile * 8 + slot * 2 + half] = ex2f(c * dx * dx);
    g_eyw[p][i48] = w * ex2f(c * dy * dy);
    g_ez [p][i48] = ex2f(c * dz * dz);

    if (i48 == 0) {
        bool act = (elements[a] != 5) && (C_expand[a] == 1);
        g_cull[p] = make_float4(px, py, pz, act ? (T_CUT / (-c)) : -1.0f);
    }
}

// ---------------------------------------------------------------------------
// Kernel 2: density. One 512-thread block per tile (16 warps); warp w handles
// pair sixteenth w: cull ballot -> iterate surviving mask bits in ascending
// pair order, reading table slices DIRECTLY from global (uniform LDG.128 for
// Ex pairs, coalesced LDG.32 for Ey/Ez). No shared staging, no inner EX2.
// Shared = 18 KB accumulators only -> 3 blocks/SM, ~48 warps resident.
// Deterministic fixed-order 16-way reduction.
// ---------------------------------------------------------------------------
#define ACC_STRIDE  (32 * (TILE_X + 1))          // per-warp acc floats (288)

__global__ __launch_bounds__(512)
void density_kernel(int npairs, float* __restrict__ out)
{
    __shared__ float s_acc[NWARP * ACC_STRIDE];  // 18 KB

    int tid  = threadIdx.x;
    int lane = tid & 31;
    int wid  = tid >> 5;
    int bid  = blockIdx.x;
    int bx = bid % NBX;
    int by = (bid / NBX) % NBY;
    int bz = bid / (NBX * NBY);

    // Tile AABB in real coordinates
    float x_lo = (float)(bx * TILE_X) * SPACING;
    float y_lo = (float)(by * TILE_Y) * SPACING;
    float z_lo = (float)(bz * TILE_Z) * SPACING;
    float x_hi = x_lo + (float)(TILE_X - 1) * SPACING;
    float y_hi = y_lo + (float)(TILE_Y - 1) * SPACING;
    float z_hi = z_lo + (float)(TILE_Z - 1) * SPACING;

    // This lane's x-row: lane -> (ty in 0..7, tz in 0..3)
    int ty = lane & 7;
    int tz = lane >> 3;
    const int ey_off = by * 8 + ty;
    const int ez_off = bz * 4 + tz;
    const int ex_off = bx * 8;

    // This warp's pair range
    int p_beg = (npairs * wid) / NWARP;
    int p_end = (npairs * (wid + 1)) / NWARP;

    // Packed accumulators: accp[i] = (sum @ x_i, sum @ x_{i+4})
    unsigned long long accp0 = 0ull, accp1 = 0ull, accp2 = 0ull, accp3 = 0ull;

    for (int c0 = p_beg; c0 < p_end; c0 += CHUNK) {
        int cend = p_end - c0;
        if (cend > CHUNK) cend = CHUNK;

        // ---- Cull one 32-pair chunk (one ballot)
        int jl = c0 + lane;
        bool sv = false;
        if (lane < cend) {
            float4 cd = g_cull[jl];
            float dx = fmaxf(fmaxf(x_lo - cd.x, cd.x - x_hi), 0.0f);
            float dy = fmaxf(fmaxf(y_lo - cd.y, cd.y - y_hi), 0.0f);
            float dz = fmaxf(fmaxf(z_lo - cd.z, cd.z - z_hi), 0.0f);
            float md2 = fmaf(dx, dx, fmaf(dy, dy, dz * dz));
            sv = (md2 <= cd.w);
        }
        unsigned m = __ballot_sync(0xffffffffu, sv);

        // ---- Iterate surviving bits in ascending pair order; read tables
        //      directly from global. Same accumulation order as compaction.
        while (m) {
            int b = __ffs(m) - 1;
            m &= m - 1;
            int j = c0 + b;

            // Ex pairs: two uniform float4 loads (broadcast within warp)
            float4 xa = *reinterpret_cast<const float4*>(&g_exp[j][ex_off]);
            float4 xb = *reinterpret_cast<const float4*>(&g_exp[j][ex_off + 4]);
            // Ey, Ez: per-lane coalesced scalar loads
            float ey = __ldg(&g_eyw[j][ey_off]);
            float ez = __ldg(&g_ez [j][ez_off]);

            float eyz = ey * ez;
            unsigned long long e2 = pk(eyz, eyz);
            accp0 = fma2(pk(xa.x, xa.y), e2, accp0);
            accp1 = fma2(pk(xa.z, xa.w), e2, accp1);
            accp2 = fma2(pk(xb.x, xb.y), e2, accp2);
            accp3 = fma2(pk(xb.z, xb.w), e2, accp3);
        }
    }

    // ---- Deposit per-warp accumulators (unpacked)
    {
        float* row = s_acc + wid * ACC_STRIDE + lane * (TILE_X + 1);
        float a0, a4, a1, a5, a2, a6, a3, a7;
        unpk(a0, a4, accp0);
        unpk(a1, a5, accp1);
        unpk(a2, a6, accp2);
        unpk(a3, a7, accp3);
        row[0] = a0; row[1] = a1; row[2] = a2; row[3] = a3;
        row[4] = a4; row[5] = a5; row[6] = a6; row[7] = a7;
    }
    __syncthreads();

    // ---- Deterministic fixed-order 16-way reduction + coalesced store.
    // First 256 threads: row l = t>>3 (32 rows), x index i = t&7.
    if (tid < 256) {
        int l = tid >> 3;
        int i = tid & 7;
        int rty = l & 7;
        int rtz = l >> 3;
        int g0 = (bz * TILE_Z + rtz) * (GRID_NX * GRID_NY)
               + (by * TILE_Y + rty) * GRID_NX
               + bx * TILE_X + i;

        float r = s_acc[l * (TILE_X + 1) + i];
#pragma unroll
        for (int w = 1; w < NWARP; w++)
            r += s_acc[w * ACC_STRIDE + l * (TILE_X + 1) + i];
        out[g0] = r;
    }
}

// ---------------------------------------------------------------------------
// Launch. Inputs (metadata order): X[800*3] f32, aw[800*6] f32, bw[800*6] f32,
// elements[800] i32, C_expand[800] i32, real_grid[110592*3] f32 (unused).
// Output: density[110592] f32.
// ---------------------------------------------------------------------------
extern "C" void kernel_launch(void* const* d_in, const int* in_sizes, int n_in,
                              void* d_out, int out_size)
{
    const float* X        = (const float*)d_in[0];
    const float* aw       = (const float*)d_in[1];
    const float* bw       = (const float*)d_in[2];
    const int*   elements = (const int*)d_in[3];
    const int*   C_expand = (const int*)d_in[4];
    float*       out      = (float*)d_out;

    int n_atoms = in_sizes[3];
    int npairs  = n_atoms * NG;

    int nthreads = npairs * 64;
    build_tables<<<(nthreads + 255) / 256, 256>>>(X, aw, bw, elements,
                                                  C_expand, npairs);

    density_kernel<<<N_TILES, 512>>>(npairs, out);
}

// round 14
// speedup vs baseline: 1.1421x; 1.1421x over previous
#include <cuda_runtime.h>
#include <cuda_bf16.h>

// Problem constants (fixed by the reference)
#define GRID_NX   48
#define GRID_NY   48
#define GRID_NZ   48
#define N_GRID    (GRID_NX * GRID_NY * GRID_NZ)   // 110592
#define SPACING   0.5f
#define A_MAX     800
#define NG        6
#define MAX_PAIRS (A_MAX * NG)                    // 4800

// Cull threshold: drop pair for a tile when |c|*min_d2 > T  (contribution < 2^-16 * w)
#define T_CUT     16.0f

// Tile geometry: 8 x 8 x 4 grid points per tile (432 tiles)
#define TILE_X 8
#define TILE_Y 8
#define TILE_Z 4
#define NBX (GRID_NX / TILE_X)   // 6
#define NBY (GRID_NY / TILE_Y)   // 6
#define NBZ (GRID_NZ / TILE_Z)   // 12
#define N_TILES (NBX * NBY * NBZ)

#define NWARP  16                // pair-range partitions (one warp each, 512 thr)
#define CHUNK  32                // pairs culled per warp-chunk (one ballot)

// Scratch (__device__ globals, no allocation)
__device__ float4 g_cull[MAX_PAIRS];        // px, py, pz, d2cut (-1 => inactive)
// Separable 1-D tables. g_exp is PAIRED layout per x-tile:
//   g_exp[p][tile*8 + slot*2 + half] = Ex(tile*8 + slot + 4*half)
__device__ float g_exp[MAX_PAIRS][48];      // Ex, paired layout
__device__ float g_eyw[MAX_PAIRS][48];      // w * Ey
__device__ float g_ez [MAX_PAIRS][48];      // Ez

__device__ __forceinline__ float ex2f(float x) {
    float r;
    asm("ex2.approx.f32 %0, %1;" : "=f"(r) : "f"(x));
    return r;
}

// Packed f32x2 helpers (Blackwell)
__device__ __forceinline__ unsigned long long pk(float lo, float hi) {
    unsigned long long r;
    asm("mov.b64 %0, {%1, %2};" : "=l"(r) : "f"(lo), "f"(hi));
    return r;
}
__device__ __forceinline__ void unpk(float& lo, float& hi, unsigned long long v) {
    asm("mov.b64 {%0, %1}, %2;" : "=f"(lo), "=f"(hi) : "l"(v));
}
__device__ __forceinline__ unsigned long long fma2(unsigned long long a,
                                                   unsigned long long b,
                                                   unsigned long long c) {
    unsigned long long r;
    asm("fma.rn.f32x2 %0, %1, %2, %3;" : "=l"(r) : "l"(a), "l"(b), "l"(c));
    return r;
}

// ---------------------------------------------------------------------------
// Kernel 1: build cull + separable tables with the OCTET RECURRENCE.
// One thread per (pair, dim, octet-of-8): 4 EX2 + two-anchor ratio chain
// yield 8 table values (345k EX2 total vs 691k for direct evaluation).
// Anchors at octet idx 0 and 4: every point is <= 1.5 A from its anchor,
// so any point with true value >= 2^-80 has a normal (non-flushed) anchor.
// Thread layout: t>>5 = pair, sub = t&31; sub in [0,18) => (dim, octet);
// sub == 18 writes the pair's cull entry. sub in [19,32) idle.
// ---------------------------------------------------------------------------
__global__ __launch_bounds__(256)
void build_tables(const float* __restrict__ X,
                  const float* __restrict__ aw,
                  const float* __restrict__ bw,
                  const int*   __restrict__ elements,
                  const int*   __restrict__ C_expand,
                  int npairs)
{
    const float LOG2E = 1.4426950408889634f;
    int t = blockIdx.x * 256 + threadIdx.x;
    int p   = t >> 5;
    int sub = t & 31;
    if (p >= npairs || sub > 18) return;

    // a = p / NG  (NG == 6), cheap reciprocal + correction
    int a = (int)(((unsigned)p * 10923u) >> 16);      // ~p/6
    if (a * NG > p) a--;
    else if ((a + 1) * NG <= p) a++;

    float c = bw[p] * LOG2E;          // c < 0

    if (sub == 18) {
        bool act = (elements[a] != 5) && (C_expand[a] == 1);
        float px = X[a * 3 + 0];
        float py = X[a * 3 + 1];
        float pz = X[a * 3 + 2];
        g_cull[p] = make_float4(px, py, pz, act ? (T_CUT / (-c)) : -1.0f);
        return;
    }

    int dim = (sub * 171) >> 10;      // sub/6 for sub<18
    int oct = sub - dim * 6;

    float base = X[a * 3 + dim];
    float g0 = (float)(oct * 8) * SPACING;
    float dx0 = g0 - base;
    float dx4 = dx0 + 2.0f;

    // Two-anchor recurrence (identical chain to the verified round-8 form):
    // r_i = 2^(c*dx_i + 0.25c),  r_{i+1} = r_i * q,  q = 2^(c/2)
    float q  = ex2f(0.5f * c);
    float e  = ex2f(c * dx0 * dx0);
    float e4 = ex2f(c * dx4 * dx4);
    float r  = ex2f(fmaf(c, dx0, 0.25f * c));

    float v0 = e;
    e *= r; r *= q; float v1 = e;
    e *= r; r *= q; float v2 = e;
    e *= r; r *= q; float v3 = e;
    r *= q;                         // r now = r4
    float v4 = e4;
    e4 *= r; r *= q; float v5 = e4;
    e4 *= r; r *= q; float v6 = e4;
    e4 *= r;         float v7 = e4;

    if (dim == 0) {
        // Paired layout: (v0,v4),(v1,v5),(v2,v6),(v3,v7)
        float4* dst = reinterpret_cast<float4*>(&g_exp[p][oct * 8]);
        dst[0] = make_float4(v0, v4, v1, v5);
        dst[1] = make_float4(v2, v6, v3, v7);
    } else if (dim == 1) {
        float w = aw[p];
        float4* dst = reinterpret_cast<float4*>(&g_eyw[p][oct * 8]);
        dst[0] = make_float4(w * v0, w * v1, w * v2, w * v3);
        dst[1] = make_float4(w * v4, w * v5, w * v6, w * v7);
    } else {
        float4* dst = reinterpret_cast<float4*>(&g_ez[p][oct * 8]);
        dst[0] = make_float4(v0, v1, v2, v3);
        dst[1] = make_float4(v4, v5, v6, v7);
    }
}

// ---------------------------------------------------------------------------
// Kernel 2: density (round-12 staged design, proven 14.5 us). One 512-thread
// block per tile (16 warps); warp w: cull its pair sixteenth -> stage
// survivor slices into shared -> pure packed-FMA accumulate, unrolled x4.
// Shared OVERLAY: slice buffers (40 KB) die after the mainloop; accumulators
// (18 KB) alias the same storage across a __syncthreads().
// ---------------------------------------------------------------------------
#define EX_STRIDE   (CHUNK * 8)
#define EY_STRIDE   (CHUNK * 8)
#define EZ_STRIDE   (CHUNK * 4)
#define EX_BASE     0
#define EY_BASE     (NWARP * EX_STRIDE)
#define EZ_BASE     (EY_BASE + NWARP * EY_STRIDE)
#define SMEM_FLOATS (EZ_BASE + NWARP * EZ_STRIDE)   // 10240 floats = 40 KB
#define ACC_STRIDE  (32 * (TILE_X + 1))             // 288 floats/warp

__global__ __launch_bounds__(512)
void density_kernel(int npairs, float* __restrict__ out)
{
    __shared__ __align__(16) float s_buf[SMEM_FLOATS];   // 40 KB, overlaid

    int tid  = threadIdx.x;
    int lane = tid & 31;
    int wid  = tid >> 5;
    int bid  = blockIdx.x;
    int bx = bid % NBX;
    int by = (bid / NBX) % NBY;
    int bz = bid / (NBX * NBY);

    float* s_ex = s_buf + EX_BASE + wid * EX_STRIDE;   // [CHUNK][8]
    float* s_ey = s_buf + EY_BASE + wid * EY_STRIDE;   // [CHUNK][8]
    float* s_ez = s_buf + EZ_BASE + wid * EZ_STRIDE;   // [CHUNK][4]

    float x_lo = (float)(bx * TILE_X) * SPACING;
    float y_lo = (float)(by * TILE_Y) * SPACING;
    float z_lo = (float)(bz * TILE_Z) * SPACING;
    float x_hi = x_lo + (float)(TILE_X - 1) * SPACING;
    float y_hi = y_lo + (float)(TILE_Y - 1) * SPACING;
    float z_hi = z_lo + (float)(TILE_Z - 1) * SPACING;

    int ty = lane & 7;
    int tz = lane >> 3;

    int p_beg = (npairs * wid) / NWARP;
    int p_end = (npairs * (wid + 1)) / NWARP;

    unsigned long long accp0 = 0ull, accp1 = 0ull, accp2 = 0ull, accp3 = 0ull;

    for (int c0 = p_beg; c0 < p_end; c0 += CHUNK) {
        int cend = p_end - c0;
        if (cend > CHUNK) cend = CHUNK;

        // ---- Cull one 32-pair chunk + stage survivor slices into shared
        int j = c0 + lane;
        bool sv = false;
        if (lane < cend) {
            float4 cd = g_cull[j];
            float dx = fmaxf(fmaxf(x_lo - cd.x, cd.x - x_hi), 0.0f);
            float dy = fmaxf(fmaxf(y_lo - cd.y, cd.y - y_hi), 0.0f);
            float dz = fmaxf(fmaxf(z_lo - cd.z, cd.z - z_hi), 0.0f);
            float md2 = fmaf(dx, dx, fmaf(dy, dy, dz * dz));
            sv = (md2 <= cd.w);
        }
        unsigned m = __ballot_sync(0xffffffffu, sv);
        int nsurv = __popc(m);
        if (sv) {
            int pos = __popc(m & ((1u << lane) - 1u));
            const float4* ex = reinterpret_cast<const float4*>(&g_exp[j][bx * 8]);
            const float4* ey = reinterpret_cast<const float4*>(&g_eyw[j][by * 8]);
            const float4* ez = reinterpret_cast<const float4*>(&g_ez [j][bz * 4]);
            reinterpret_cast<float4*>(s_ex + pos * 8)[0] = ex[0];
            reinterpret_cast<float4*>(s_ex + pos * 8)[1] = ex[1];
            reinterpret_cast<float4*>(s_ey + pos * 8)[0] = ey[0];
            reinterpret_cast<float4*>(s_ey + pos * 8)[1] = ey[1];
            reinterpret_cast<float4*>(s_ez + pos * 4)[0] = ez[0];
        }
        __syncwarp();

        // ---- Accumulate: pure packed FMAs, unrolled x4 for LDS MLP
        int s = 0;
        for (; s + 4 <= nsurv; s += 4) {
            float eyzA = s_ey[(s    ) * 8 + ty] * s_ez[(s    ) * 4 + tz];
            float eyzB = s_ey[(s + 1) * 8 + ty] * s_ez[(s + 1) * 4 + tz];
            float eyzC = s_ey[(s + 2) * 8 + ty] * s_ez[(s + 2) * 4 + tz];
            float eyzD = s_ey[(s + 3) * 8 + ty] * s_ez[(s + 3) * 4 + tz];
            unsigned long long eA = pk(eyzA, eyzA);
            unsigned long long eB = pk(eyzB, eyzB);
            unsigned long long eC = pk(eyzC, eyzC);
            unsigned long long eD = pk(eyzD, eyzD);
            const unsigned long long* xA =
                reinterpret_cast<const unsigned long long*>(s_ex + (s    ) * 8);
            const unsigned long long* xB =
                reinterpret_cast<const unsigned long long*>(s_ex + (s + 1) * 8);
            const unsigned long long* xC =
                reinterpret_cast<const unsigned long long*>(s_ex + (s + 2) * 8);
            const unsigned long long* xD =
                reinterpret_cast<const unsigned long long*>(s_ex + (s + 3) * 8);
            accp0 = fma2(xA[0], eA, accp0);
            accp1 = fma2(xA[1], eA, accp1);
            accp2 = fma2(xA[2], eA, accp2);
            accp3 = fma2(xA[3], eA, accp3);
            accp0 = fma2(xB[0], eB, accp0);
            accp1 = fma2(xB[1], eB, accp1);
            accp2 = fma2(xB[2], eB, accp2);
            accp3 = fma2(xB[3], eB, accp3);
            accp0 = fma2(xC[0], eC, accp0);
            accp1 = fma2(xC[1], eC, accp1);
            accp2 = fma2(xC[2], eC, accp2);
            accp3 = fma2(xC[3], eC, accp3);
            accp0 = fma2(xD[0], eD, accp0);
            accp1 = fma2(xD[1], eD, accp1);
            accp2 = fma2(xD[2], eD, accp2);
            accp3 = fma2(xD[3], eD, accp3);
        }
        for (; s < nsurv; s++) {
            float eyz = s_ey[s * 8 + ty] * s_ez[s * 4 + tz];
            unsigned long long e2 = pk(eyz, eyz);
            const unsigned long long* xp =
                reinterpret_cast<const unsigned long long*>(s_ex + s * 8);
            accp0 = fma2(xp[0], e2, accp0);
            accp1 = fma2(xp[1], e2, accp1);
            accp2 = fma2(xp[2], e2, accp2);
            accp3 = fma2(xp[3], e2, accp3);
        }
        __syncwarp();   // protect this warp's shared slices before refill
    }

    // ---- Slice buffers dead; alias the storage as accumulators.
    __syncthreads();
    float* s_acc = s_buf;                        // [NWARP][32][TILE_X+1]
    {
        float* row = s_acc + wid * ACC_STRIDE + lane * (TILE_X + 1);
        float a0, a4, a1, a5, a2, a6, a3, a7;
        unpk(a0, a4, accp0);
        unpk(a1, a5, accp1);
        unpk(a2, a6, accp2);
        unpk(a3, a7, accp3);
        row[0] = a0; row[1] = a1; row[2] = a2; row[3] = a3;
        row[4] = a4; row[5] = a5; row[6] = a6; row[7] = a7;
    }
    __syncthreads();

    // ---- Deterministic fixed-order 16-way reduction + coalesced store.
    if (tid < 256) {
        int l = tid >> 3;
        int i = tid & 7;
        int rty = l & 7;
        int rtz = l >> 3;
        int g0 = (bz * TILE_Z + rtz) * (GRID_NX * GRID_NY)
               + (by * TILE_Y + rty) * GRID_NX
               + bx * TILE_X + i;

        float r = s_acc[l * (TILE_X + 1) + i];
#pragma unroll
        for (int w = 1; w < NWARP; w++)
            r += s_acc[w * ACC_STRIDE + l * (TILE_X + 1) + i];
        out[g0] = r;
    }
}

// ---------------------------------------------------------------------------
// Launch. Inputs (metadata order): X[800*3] f32, aw[800*6] f32, bw[800*6] f32,
// elements[800] i32, C_expand[800] i32, real_grid[110592*3] f32 (unused).
// Output: density[110592] f32.
// ---------------------------------------------------------------------------
extern "C" void kernel_launch(void* const* d_in, const int* in_sizes, int n_in,
                              void* d_out, int out_size)
{
    const float* X        = (const float*)d_in[0];
    const float* aw       = (const float*)d_in[1];
    const float* bw       = (const float*)d_in[2];
    const int*   elements = (const int*)d_in[3];
    const int*   C_expand = (const int*)d_in[4];
    float*       out      = (float*)d_out;

    int n_atoms = in_sizes[3];
    int npairs  = n_atoms * NG;

    int nthreads = npairs * 32;
    build_tables<<<(nthreads + 255) / 256, 256>>>(X, aw, bw, elements,
                                                  C_expand, npairs);

    density_kernel<<<N_TILES, 512>>>(npairs, out);
}

// round 15
// speedup vs baseline: 1.2249x; 1.0725x over previous
#include <cuda_runtime.h>
#include <cuda_bf16.h>

// Problem constants (fixed by the reference)
#define GRID_NX   48
#define GRID_NY   48
#define GRID_NZ   48
#define N_GRID    (GRID_NX * GRID_NY * GRID_NZ)   // 110592
#define SPACING   0.5f
#define A_MAX     800
#define NG        6
#define MAX_PAIRS (A_MAX * NG)                    // 4800

// Cull threshold: drop pair for a tile when |c|*min_d2 > T  (contribution < 2^-16 * w)
#define T_CUT     16.0f

// Tile geometry: 8 x 8 x 4 grid points per tile (432 tiles)
#define TILE_X 8
#define TILE_Y 8
#define TILE_Z 4
#define NBX (GRID_NX / TILE_X)   // 6
#define NBY (GRID_NY / TILE_Y)   // 6
#define NBZ (GRID_NZ / TILE_Z)   // 12
#define N_TILES (NBX * NBY * NBZ)

#define NWARP  16                // pair-range partitions (one warp each, 512 thr)
#define CHUNK  32                // pairs culled per warp-chunk (one ballot)

// Scratch (__device__ globals, no allocation)
__device__ float4 g_cull[MAX_PAIRS];        // px, py, pz, d2cut (-1 => inactive)
// Separable 1-D tables. g_exp is PAIRED layout per x-tile:
//   g_exp[p][tile*8 + slot*2 + half] = Ex(tile*8 + slot + 4*half)
__device__ float g_exp[MAX_PAIRS][48];      // Ex, paired layout
__device__ float g_eyw[MAX_PAIRS][48];      // w * Ey
__device__ float g_ez [MAX_PAIRS][48];      // Ez

__device__ __forceinline__ float ex2f(float x) {
    float r;
    asm("ex2.approx.f32 %0, %1;" : "=f"(r) : "f"(x));
    return r;
}

// Packed f32x2 helpers (Blackwell)
__device__ __forceinline__ unsigned long long pk(float lo, float hi) {
    unsigned long long r;
    asm("mov.b64 %0, {%1, %2};" : "=l"(r) : "f"(lo), "f"(hi));
    return r;
}
__device__ __forceinline__ void unpk(float& lo, float& hi, unsigned long long v) {
    asm("mov.b64 {%0, %1}, %2;" : "=f"(lo), "=f"(hi) : "l"(v));
}
__device__ __forceinline__ unsigned long long fma2(unsigned long long a,
                                                   unsigned long long b,
                                                   unsigned long long c) {
    unsigned long long r;
    asm("fma.rn.f32x2 %0, %1, %2, %3;" : "=l"(r) : "l"(a), "l"(b), "l"(c));
    return r;
}

// ---------------------------------------------------------------------------
// Kernel 1: build cull table + separable 1-D exp tables.
// (Round-12 version restored: one thread per (pair, grid index i48), three
// INDEPENDENT EX2s per thread, 230k threads — measured-fastest build shape.)
// ---------------------------------------------------------------------------
__global__ __launch_bounds__(256)
void build_tables(const float* __restrict__ X,
                  const float* __restrict__ aw,
                  const float* __restrict__ bw,
                  const int*   __restrict__ elements,
                  const int*   __restrict__ C_expand,
                  int npairs)
{
    const float LOG2E = 1.4426950408889634f;
    int t = blockIdx.x * 256 + threadIdx.x;
    int p   = t / 48;
    int i48 = t % 48;
    if (p >= npairs) return;
    int a = p / NG;

    float c = bw[p] * LOG2E;          // c < 0
    float w = aw[p];
    float px = X[a * 3 + 0];
    float py = X[a * 3 + 1];
    float pz = X[a * 3 + 2];

    float g = (float)i48 * SPACING;
    float dx = g - px, dy = g - py, dz = g - pz;

    // Ex in paired layout
    int tile = i48 >> 3, ii = i48 & 7;
    int slot = ii & 3, half = ii >> 2;
    g_exp[p][tile * 8 + slot * 2 + half] = ex2f(c * dx * dx);
    g_eyw[p][i48] = w * ex2f(c * dy * dy);
    g_ez [p][i48] = ex2f(c * dz * dz);

    if (i48 == 0) {
        bool act = (elements[a] != 5) && (C_expand[a] == 1);
        g_cull[p] = make_float4(px, py, pz, act ? (T_CUT / (-c)) : -1.0f);
    }
}

// ---------------------------------------------------------------------------
// Kernel 2: density (round-12 staged design). One 512-thread block per tile
// (16 warps); warp w: cull its pair sixteenth -> stage survivor slices into
// shared -> pure packed-FMA accumulate (no EX2), unrolled x4, with Ex read
// as TWO LDS.128 per survivor (ulonglong2) instead of four LDS.64.
// Shared OVERLAY: slice buffers (40 KB) die after the mainloop; accumulators
// (18 KB) alias the same storage across a __syncthreads().
// ---------------------------------------------------------------------------
#define EX_STRIDE   (CHUNK * 8)
#define EY_STRIDE   (CHUNK * 8)
#define EZ_STRIDE   (CHUNK * 4)
#define EX_BASE     0
#define EY_BASE     (NWARP * EX_STRIDE)
#define EZ_BASE     (EY_BASE + NWARP * EY_STRIDE)
#define SMEM_FLOATS (EZ_BASE + NWARP * EZ_STRIDE)   // 10240 floats = 40 KB
#define ACC_STRIDE  (32 * (TILE_X + 1))             // 288 floats/warp

__global__ __launch_bounds__(512)
void density_kernel(int npairs, float* __restrict__ out)
{
    __shared__ __align__(16) float s_buf[SMEM_FLOATS];   // 40 KB, overlaid

    int tid  = threadIdx.x;
    int lane = tid & 31;
    int wid  = tid >> 5;
    int bid  = blockIdx.x;
    int bx = bid % NBX;
    int by = (bid / NBX) % NBY;
    int bz = bid / (NBX * NBY);

    float* s_ex = s_buf + EX_BASE + wid * EX_STRIDE;   // [CHUNK][8]
    float* s_ey = s_buf + EY_BASE + wid * EY_STRIDE;   // [CHUNK][8]
    float* s_ez = s_buf + EZ_BASE + wid * EZ_STRIDE;   // [CHUNK][4]

    float x_lo = (float)(bx * TILE_X) * SPACING;
    float y_lo = (float)(by * TILE_Y) * SPACING;
    float z_lo = (float)(bz * TILE_Z) * SPACING;
    float x_hi = x_lo + (float)(TILE_X - 1) * SPACING;
    float y_hi = y_lo + (float)(TILE_Y - 1) * SPACING;
    float z_hi = z_lo + (float)(TILE_Z - 1) * SPACING;

    int ty = lane & 7;
    int tz = lane >> 3;
    const float* s_ey_t = s_ey + ty;     // hoisted lane offsets
    const float* s_ez_t = s_ez + tz;

    int p_beg = (npairs * wid) / NWARP;
    int p_end = (npairs * (wid + 1)) / NWARP;

    unsigned long long accp0 = 0ull, accp1 = 0ull, accp2 = 0ull, accp3 = 0ull;

    for (int c0 = p_beg; c0 < p_end; c0 += CHUNK) {
        int cend = p_end - c0;
        if (cend > CHUNK) cend = CHUNK;

        // ---- Cull one 32-pair chunk + stage survivor slices into shared
        int j = c0 + lane;
        bool sv = false;
        if (lane < cend) {
            float4 cd = g_cull[j];
            float dx = fmaxf(fmaxf(x_lo - cd.x, cd.x - x_hi), 0.0f);
            float dy = fmaxf(fmaxf(y_lo - cd.y, cd.y - y_hi), 0.0f);
            float dz = fmaxf(fmaxf(z_lo - cd.z, cd.z - z_hi), 0.0f);
            float md2 = fmaf(dx, dx, fmaf(dy, dy, dz * dz));
            sv = (md2 <= cd.w);
        }
        unsigned m = __ballot_sync(0xffffffffu, sv);
        int nsurv = __popc(m);
        if (sv) {
            int pos = __popc(m & ((1u << lane) - 1u));
            const float4* ex = reinterpret_cast<const float4*>(&g_exp[j][bx * 8]);
            const float4* ey = reinterpret_cast<const float4*>(&g_eyw[j][by * 8]);
            const float4* ez = reinterpret_cast<const float4*>(&g_ez [j][bz * 4]);
            reinterpret_cast<float4*>(s_ex + pos * 8)[0] = ex[0];
            reinterpret_cast<float4*>(s_ex + pos * 8)[1] = ex[1];
            reinterpret_cast<float4*>(s_ey + pos * 8)[0] = ey[0];
            reinterpret_cast<float4*>(s_ey + pos * 8)[1] = ey[1];
            reinterpret_cast<float4*>(s_ez + pos * 4)[0] = ez[0];
        }
        __syncwarp();

        // ---- Accumulate: pure packed FMAs; Ex via 2x LDS.128 per survivor
        int s = 0;
        for (; s + 4 <= nsurv; s += 4) {
            float eyzA = s_ey_t[(s    ) * 8] * s_ez_t[(s    ) * 4];
            float eyzB = s_ey_t[(s + 1) * 8] * s_ez_t[(s + 1) * 4];
            float eyzC = s_ey_t[(s + 2) * 8] * s_ez_t[(s + 2) * 4];
            float eyzD = s_ey_t[(s + 3) * 8] * s_ez_t[(s + 3) * 4];
            unsigned long long eA = pk(eyzA, eyzA);
            unsigned long long eB = pk(eyzB, eyzB);
            unsigned long long eC = pk(eyzC, eyzC);
            unsigned long long eD = pk(eyzD, eyzD);
            ulonglong2 xA0 = *reinterpret_cast<const ulonglong2*>(s_ex + (s    ) * 8);
            ulonglong2 xA1 = *reinterpret_cast<const ulonglong2*>(s_ex + (s    ) * 8 + 4);
            ulonglong2 xB0 = *reinterpret_cast<const ulonglong2*>(s_ex + (s + 1) * 8);
            ulonglong2 xB1 = *reinterpret_cast<const ulonglong2*>(s_ex + (s + 1) * 8 + 4);
            ulonglong2 xC0 = *reinterpret_cast<const ulonglong2*>(s_ex + (s + 2) * 8);
            ulonglong2 xC1 = *reinterpret_cast<const ulonglong2*>(s_ex + (s + 2) * 8 + 4);
            ulonglong2 xD0 = *reinterpret_cast<const ulonglong2*>(s_ex + (s + 3) * 8);
            ulonglong2 xD1 = *reinterpret_cast<const ulonglong2*>(s_ex + (s + 3) * 8 + 4);
            accp0 = fma2(xA0.x, eA, accp0);
            accp1 = fma2(xA0.y, eA, accp1);
            accp2 = fma2(xA1.x, eA, accp2);
            accp3 = fma2(xA1.y, eA, accp3);
            accp0 = fma2(xB0.x, eB, accp0);
            accp1 = fma2(xB0.y, eB, accp1);
            accp2 = fma2(xB1.x, eB, accp2);
            accp3 = fma2(xB1.y, eB, accp3);
            accp0 = fma2(xC0.x, eC, accp0);
            accp1 = fma2(xC0.y, eC, accp1);
            accp2 = fma2(xC1.x, eC, accp2);
            accp3 = fma2(xC1.y, eC, accp3);
            accp0 = fma2(xD0.x, eD, accp0);
            accp1 = fma2(xD0.y, eD, accp1);
            accp2 = fma2(xD1.x, eD, accp2);
            accp3 = fma2(xD1.y, eD, accp3);
        }
        for (; s < nsurv; s++) {
            float eyz = s_ey_t[s * 8] * s_ez_t[s * 4];
            unsigned long long e2 = pk(eyz, eyz);
            ulonglong2 x0 = *reinterpret_cast<const ulonglong2*>(s_ex + s * 8);
            ulonglong2 x1 = *reinterpret_cast<const ulonglong2*>(s_ex + s * 8 + 4);
            accp0 = fma2(x0.x, e2, accp0);
            accp1 = fma2(x0.y, e2, accp1);
            accp2 = fma2(x1.x, e2, accp2);
            accp3 = fma2(x1.y, e2, accp3);
        }
        __syncwarp();   // protect this warp's shared slices before refill
    }

    // ---- Slice buffers dead; alias the storage as accumulators.
    __syncthreads();
    float* s_acc = s_buf;                        // [NWARP][32][TILE_X+1]
    {
        float* row = s_acc + wid * ACC_STRIDE + lane * (TILE_X + 1);
        float a0, a4, a1, a5, a2, a6, a3, a7;
        unpk(a0, a4, accp0);
        unpk(a1, a5, accp1);
        unpk(a2, a6, accp2);
        unpk(a3, a7, accp3);
        row[0] = a0; row[1] = a1; row[2] = a2; row[3] = a3;
        row[4] = a4; row[5] = a5; row[6] = a6; row[7] = a7;
    }
    __syncthreads();

    // ---- Deterministic fixed-order 16-way reduction + coalesced store.
    if (tid < 256) {
        int l = tid >> 3;
        int i = tid & 7;
        int rty = l & 7;
        int rtz = l >> 3;
        int g0 = (bz * TILE_Z + rtz) * (GRID_NX * GRID_NY)
               + (by * TILE_Y + rty) * GRID_NX
               + bx * TILE_X + i;

        float r = s_acc[l * (TILE_X + 1) + i];
#pragma unroll
        for (int w = 1; w < NWARP; w++)
            r += s_acc[w * ACC_STRIDE + l * (TILE_X + 1) + i];
        out[g0] = r;
    }
}

// ---------------------------------------------------------------------------
// Launch. Inputs (metadata order): X[800*3] f32, aw[800*6] f32, bw[800*6] f32,
// elements[800] i32, C_expand[800] i32, real_grid[110592*3] f32 (unused).
// Output: density[110592] f32.
// ---------------------------------------------------------------------------
extern "C" void kernel_launch(void* const* d_in, const int* in_sizes, int n_in,
                              void* d_out, int out_size)
{
    const float* X        = (const float*)d_in[0];
    const float* aw       = (const float*)d_in[1];
    const float* bw       = (const float*)d_in[2];
    const int*   elements = (const int*)d_in[3];
    const int*   C_expand = (const int*)d_in[4];
    float*       out      = (float*)d_out;

    int n_atoms = in_sizes[3];
    int npairs  = n_atoms * NG;

    int nthreads = npairs * 48;
    build_tables<<<(nthreads + 255) / 256, 256>>>(X, aw, bw, elements,
                                                  C_expand, npairs);

    density_kernel<<<N_TILES, 512>>>(npairs, out);
}